// round 14
// baseline (speedup 1.0000x reference)
#include <cuda_runtime.h>
#include <cuda_fp16.h>
#include <math.h>
#include <stdint.h>

#define DIM     1024
#define HIDDEN  1024
#define NE      8
#define T_TOK   32768
#define KT      64          // k-tile in halfs (128B of fp16)
#define NKT     16          // 1024 / 64
#define SHB     144         // padded smem row bytes (72 halfs)

// ---------------- device scratch ----------------
__device__ int    g_count[NE];
__device__ int    g_tok[NE * T_TOK];
__device__ float  g_wt[NE * T_TOK];
__device__ __align__(16) __half g_x16[(size_t)T_TOK * DIM];
__device__ __align__(16) __half g_wg16[(size_t)NE * HIDDEN * DIM];
__device__ __align__(16) __half g_wu16[(size_t)NE * HIDDEN * DIM];
__device__ __align__(16) __half g_wd16[(size_t)NE * DIM * HIDDEN];
__device__ __align__(16) __half g_h[(size_t)NE * T_TOK * HIDDEN];   // uncompacted: [e][slot][H]

// ---------------- helpers ----------------
__device__ __forceinline__ uint32_t sptr(const void* p) {
    return (uint32_t)__cvta_generic_to_shared(p);
}
__device__ __forceinline__ void cp16(uint32_t dst, const void* src) {
    asm volatile("cp.async.cg.shared.global [%0], [%1], 16;" :: "r"(dst), "l"(src));
}
__device__ __forceinline__ void cp_commit() {
    asm volatile("cp.async.commit_group;" ::: "memory");
}
template<int N> __device__ __forceinline__ void cp_wait() {
    asm volatile("cp.async.wait_group %0;" :: "n"(N) : "memory");
}
__device__ __forceinline__ void ldsm4(uint32_t* r, uint32_t a) {
    asm volatile("ldmatrix.sync.aligned.m8n8.x4.shared.b16 {%0,%1,%2,%3}, [%4];"
                 : "=r"(r[0]), "=r"(r[1]), "=r"(r[2]), "=r"(r[3]) : "r"(a));
}
__device__ __forceinline__ void mma16(float* c, const uint32_t* a, uint32_t b0, uint32_t b1) {
    asm volatile("mma.sync.aligned.m16n8k16.row.col.f32.f16.f16.f32 "
                 "{%0,%1,%2,%3},{%4,%5,%6,%7},{%8,%9},{%0,%1,%2,%3};"
                 : "+f"(c[0]), "+f"(c[1]), "+f"(c[2]), "+f"(c[3])
                 : "r"(a[0]), "r"(a[1]), "r"(a[2]), "r"(a[3]), "r"(b0), "r"(b1));
}
__device__ __forceinline__ float silu(float g) {
    return g * (1.f / (1.f + __expf(-g)));
}

// ---------------- fused prep: wg/wu conversion + router (2 tokens/warp) ----------------
#define CONVB   (NE * HIDDEN * DIM / 4 / 256)   // 8192 blocks per weight tensor
#define ROUTB   (T_TOK / 16)                    // 2048 router blocks (2 tokens per warp)
__global__ __launch_bounds__(256) void k_prep(const float* __restrict__ x,
                                              const float* __restrict__ gate_w,
                                              const float* __restrict__ wg,
                                              const float* __restrict__ wu) {
    int b = blockIdx.x;
    if (b >= ROUTB) {
        // -------- weight conversion (gate_proj / up_proj only) --------
        int cb    = b - ROUTB;
        int which = cb / CONVB;
        const float* s = (which == 0) ? wg : wu;
        __half* d = (which == 0) ? g_wg16 : g_wu16;
        int i = (cb - which * CONVB) * 256 + threadIdx.x;
        float4 v = ((const float4*)s)[i];
        __half2* o = (__half2*)d + (size_t)i * 2;
        o[0] = __floats2half2_rn(v.x, v.y);
        o[1] = __floats2half2_rn(v.z, v.w);
        return;
    }
    // -------- router: each warp handles TWO tokens (independent streams -> 2x MLP) --------
    int wgl  = b * 8 + (threadIdx.x >> 5);   // warp-global id, 0..T_TOK/2-1
    int lane = threadIdx.x & 31;
    int t0 = wgl * 2, t1 = t0 + 1;
    const float* xr0 = x + (size_t)t0 * DIM;
    const float* xr1 = x + (size_t)t1 * DIM;
    __half* xo0 = g_x16 + (size_t)t0 * DIM;
    __half* xo1 = g_x16 + (size_t)t1 * DIM;

    float acc0[NE], acc1[NE];
    #pragma unroll
    for (int e = 0; e < NE; e++) { acc0[e] = 0.f; acc1[e] = 0.f; }

    float4 xv0 = *(const float4*)(xr0 + lane * 4);
    float4 xv1 = *(const float4*)(xr1 + lane * 4);
    #pragma unroll
    for (int j = 0; j < DIM / 128; j++) {
        int d = j * 128 + lane * 4;
        float4 xn0, xn1;
        if (j + 1 < DIM / 128) {
            xn0 = *(const float4*)(xr0 + d + 128);
            xn1 = *(const float4*)(xr1 + d + 128);
        }
        *(__half2*)(xo0 + d)     = __floats2half2_rn(xv0.x, xv0.y);
        *(__half2*)(xo0 + d + 2) = __floats2half2_rn(xv0.z, xv0.w);
        *(__half2*)(xo1 + d)     = __floats2half2_rn(xv1.x, xv1.y);
        *(__half2*)(xo1 + d + 2) = __floats2half2_rn(xv1.z, xv1.w);
        #pragma unroll
        for (int e = 0; e < NE; e++) {
            float4 gv = *(const float4*)(gate_w + e * DIM + d);
            acc0[e] += xv0.x * gv.x + xv0.y * gv.y + xv0.z * gv.z + xv0.w * gv.w;
            acc1[e] += xv1.x * gv.x + xv1.y * gv.y + xv1.z * gv.z + xv1.w * gv.w;
        }
        xv0 = xn0; xv1 = xn1;
    }
    #pragma unroll
    for (int off = 16; off > 0; off >>= 1)
        #pragma unroll
        for (int e = 0; e < NE; e++) {
            acc0[e] += __shfl_xor_sync(0xffffffffu, acc0[e], off);
            acc1[e] += __shfl_xor_sync(0xffffffffu, acc1[e], off);
        }
    if (lane == 0) {
        #pragma unroll
        for (int t = 0; t < 2; t++) {
            float* acc = t ? acc1 : acc0;
            int tok = t ? t1 : t0;
            int i0 = 0;
            #pragma unroll
            for (int e = 1; e < NE; e++) if (acc[e] > acc[i0]) i0 = e;
            int i1 = -1;
            #pragma unroll
            for (int e = 0; e < NE; e++) {
                if (e == i0) continue;
                if (i1 < 0 || acc[e] > acc[i1]) i1 = e;
            }
            float s0 = 1.f / (1.f + __expf(-acc[i0]));
            float s1 = 1.f / (1.f + __expf(-acc[i1]));
            float inv = 1.f / (s0 + s1 + 1e-9f);
            int p0 = atomicAdd(&g_count[i0], 1);
            g_tok[i0 * T_TOK + p0] = tok; g_wt[i0 * T_TOK + p0] = s0 * inv;
            int p1 = atomicAdd(&g_count[i1], 1);
            g_tok[i1 * T_TOK + p1] = tok; g_wt[i1 * T_TOK + p1] = s1 * inv;
        }
    }
}

// ---------------- GEMM1 (fp16 mma): h = silu(Xg Wg^T) * (Xg Wu^T) ----------------
// Block 128(M) x 64(N) dual-B, 256 thr, 3-stage cp.async pipeline, one barrier/iter.
// z-slice NE carries the down_proj fp32->fp16 conversion (rides gemm1's idle DRAM bandwidth).
#define G1_BUF  (256 * SHB)
#define G1_SMEM (3 * G1_BUF)
__global__ __launch_bounds__(256, 2) void k_gemm1(const float* __restrict__ wd) {
    extern __shared__ char smem[];
    if (blockIdx.z == NE) {
        int bi = blockIdx.y * gridDim.x + blockIdx.x;          // 0..4095
        int i0 = (bi * 256 + (int)threadIdx.x) * 2;
        #pragma unroll
        for (int k = 0; k < 2; k++) {
            int i = i0 + k;
            float4 v = ((const float4*)wd)[i];
            __half2* o = (__half2*)g_wd16 + (size_t)i * 2;
            o[0] = __floats2half2_rn(v.x, v.y);
            o[1] = __floats2half2_rn(v.z, v.w);
        }
        return;
    }
    int e   = blockIdx.z;
    int cnt = g_count[e];
    int m0  = blockIdx.y * 128;
    if (m0 >= cnt) return;
    int n0  = blockIdx.x * 64;
    int tid = threadIdx.x, lane = tid & 31, wid = tid >> 5;
    int wm  = wid & 3, wn = wid >> 2;

    const __half* Wg = g_wg16 + (size_t)e * HIDDEN * DIM;
    const __half* Wu = g_wu16 + (size_t)e * HIDDEN * DIM;

    const __half* arow[4];
    #pragma unroll
    for (int it = 0; it < 4; it++) {
        int flat = tid + it * 256;
        int m    = flat >> 3;
        int gm   = m0 + m;
        int tok  = g_tok[e * T_TOK + (gm < cnt ? gm : 0)];
        arow[it] = g_x16 + (size_t)tok * DIM + (flat & 7) * 8;
    }
    const __half* grow[2];
    const __half* urow[2];
    #pragma unroll
    for (int it = 0; it < 2; it++) {
        int flat = tid + it * 256;
        int n    = flat >> 3;
        grow[it] = Wg + (size_t)(n0 + n) * DIM + (flat & 7) * 8;
        urow[it] = Wu + (size_t)(n0 + n) * DIM + (flat & 7) * 8;
    }
    uint32_t sbase = sptr(smem);
    uint32_t dA[4], dG[2], dU[2];
    #pragma unroll
    for (int it = 0; it < 4; it++) {
        int flat = tid + it * 256;
        dA[it] = sbase + (uint32_t)((flat >> 3) * SHB + (flat & 7) * 16);
    }
    #pragma unroll
    for (int it = 0; it < 2; it++) {
        int flat = tid + it * 256;
        dG[it] = sbase + (uint32_t)(128 * SHB + (flat >> 3) * SHB + (flat & 7) * 16);
        dU[it] = sbase + (uint32_t)(192 * SHB + (flat >> 3) * SHB + (flat & 7) * 16);
    }

    float accg[2][4][4], accu[2][4][4];
    #pragma unroll
    for (int mt = 0; mt < 2; mt++)
        #pragma unroll
        for (int nt = 0; nt < 4; nt++)
            #pragma unroll
            for (int i = 0; i < 4; i++) { accg[mt][nt][i] = 0.f; accu[mt][nt][i] = 0.f; }

    uint32_t aOff = (uint32_t)((wm * 32 + (lane & 15)) * SHB + ((lane >> 4) & 1) * 16);
    uint32_t bRow = (uint32_t)(wn * 32 + (lane & 7) + ((lane >> 4) & 1) * 8);
    uint32_t gOff = 128 * SHB + bRow * SHB + ((lane >> 3) & 1) * 16;
    uint32_t uOff = 192 * SHB + bRow * SHB + ((lane >> 3) & 1) * 16;

    #pragma unroll
    for (int it = 0; it < 4; it++) cp16(dA[it], arow[it]);
    #pragma unroll
    for (int it = 0; it < 2; it++) { cp16(dG[it], grow[it]); cp16(dU[it], urow[it]); }
    cp_commit();
    #pragma unroll
    for (int it = 0; it < 4; it++) cp16(dA[it] + G1_BUF, arow[it] + KT);
    #pragma unroll
    for (int it = 0; it < 2; it++) { cp16(dG[it] + G1_BUF, grow[it] + KT); cp16(dU[it] + G1_BUF, urow[it] + KT); }
    cp_commit();

    for (int kt = 0; kt < NKT; kt++) {
        uint32_t cur = (uint32_t)((kt % 3) * G1_BUF);
        if (kt == NKT - 1) cp_wait<0>(); else cp_wait<1>();
        __syncthreads();

        if (kt + 2 < NKT) {
            uint32_t nxt = (uint32_t)(((kt + 2) % 3) * G1_BUF);
            int ko = (kt + 2) * KT;
            #pragma unroll
            for (int it = 0; it < 4; it++) cp16(dA[it] + nxt, arow[it] + ko);
            #pragma unroll
            for (int it = 0; it < 2; it++) { cp16(dG[it] + nxt, grow[it] + ko); cp16(dU[it] + nxt, urow[it] + ko); }
            cp_commit();
        }

        uint32_t aB = sbase + cur + aOff;
        uint32_t gB = sbase + cur + gOff;
        uint32_t uB = sbase + cur + uOff;
        #pragma unroll
        for (int ks = 0; ks < 4; ks++) {
            uint32_t a[2][4], bg[2][4], bu[2][4];
            ldsm4(a[0], aB + ks * 32);
            ldsm4(a[1], aB + 16 * SHB + ks * 32);
            ldsm4(bg[0], gB + ks * 32);
            ldsm4(bg[1], gB + 16 * SHB + ks * 32);
            ldsm4(bu[0], uB + ks * 32);
            ldsm4(bu[1], uB + 16 * SHB + ks * 32);
            #pragma unroll
            for (int mt = 0; mt < 2; mt++)
                #pragma unroll
                for (int nt = 0; nt < 4; nt++) {
                    int g = nt >> 1, h = (nt & 1) * 2;
                    mma16(accg[mt][nt], a[mt], bg[g][h], bg[g][h + 1]);
                    mma16(accu[mt][nt], a[mt], bu[g][h], bu[g][h + 1]);
                }
        }
    }

    size_t base = (size_t)e * T_TOK;
    #pragma unroll
    for (int mt = 0; mt < 2; mt++) {
        #pragma unroll
        for (int half = 0; half < 2; half++) {
            int gm = m0 + wm * 32 + mt * 16 + (lane >> 2) + half * 8;
            if (gm < cnt) {
                __half* hp = &g_h[(base + gm) * HIDDEN + n0 + wn * 32 + (lane & 3) * 2];
                #pragma unroll
                for (int nt = 0; nt < 4; nt++) {
                    float gx = accg[mt][nt][half * 2 + 0], ux = accu[mt][nt][half * 2 + 0];
                    float gy = accg[mt][nt][half * 2 + 1], uy = accu[mt][nt][half * 2 + 1];
                    *(__half2*)(hp + nt * 8) = __floats2half2_rn(silu(gx) * ux, silu(gy) * uy);
                }
            }
        }
    }
}

// ---------------- GEMM2 (fp16 mma): out += (h Wd^T) * wt  (atomic, 2 adds/elem) ----------------
#define G2_BUF  (256 * SHB)
#define G2_SMEM (3 * G2_BUF)
__global__ __launch_bounds__(256, 2) void k_gemm2(float* __restrict__ out) {
    extern __shared__ char smem[];
    int e   = blockIdx.z;
    int cnt = g_count[e];
    int m0  = blockIdx.y * 128;
    if (m0 >= cnt) return;
    int n0  = blockIdx.x * 128;
    int tid = threadIdx.x, lane = tid & 31, wid = tid >> 5;
    int wm  = wid & 1, wn = wid >> 1;

    const __half* Wd = g_wd16 + (size_t)e * DIM * HIDDEN;
    size_t base = (size_t)e * T_TOK;

    const __half* arow[4];
    const __half* brow[4];
    #pragma unroll
    for (int it = 0; it < 4; it++) {
        int flat = tid + it * 256;
        int m    = flat >> 3;
        int gm   = m0 + m;
        arow[it] = g_h + (base + (gm < cnt ? gm : 0)) * HIDDEN + (flat & 7) * 8;
        brow[it] = Wd + (size_t)(n0 + m) * HIDDEN + (flat & 7) * 8;
    }
    uint32_t sbase = sptr(smem);
    uint32_t dA[4], dB[4];
    #pragma unroll
    for (int it = 0; it < 4; it++) {
        int flat = tid + it * 256;
        dA[it] = sbase + (uint32_t)((flat >> 3) * SHB + (flat & 7) * 16);
        dB[it] = dA[it] + 128 * SHB;
    }

    float acc[4][4][4];
    #pragma unroll
    for (int mt = 0; mt < 4; mt++)
        #pragma unroll
        for (int nt = 0; nt < 4; nt++)
            #pragma unroll
            for (int i = 0; i < 4; i++) acc[mt][nt][i] = 0.f;

    uint32_t aOff = (uint32_t)((wm * 64 + (lane & 15)) * SHB + ((lane >> 4) & 1) * 16);
    uint32_t bOff = 128 * SHB +
                    (uint32_t)((wn * 32 + (lane & 7) + ((lane >> 4) & 1) * 8) * SHB +
                               ((lane >> 3) & 1) * 16);

    #pragma unroll
    for (int it = 0; it < 4; it++) { cp16(dA[it], arow[it]); cp16(dB[it], brow[it]); }
    cp_commit();
    #pragma unroll
    for (int it = 0; it < 4; it++) { cp16(dA[it] + G2_BUF, arow[it] + KT); cp16(dB[it] + G2_BUF, brow[it] + KT); }
    cp_commit();

    for (int kt = 0; kt < NKT; kt++) {
        uint32_t cur = (uint32_t)((kt % 3) * G2_BUF);
        if (kt == NKT - 1) cp_wait<0>(); else cp_wait<1>();
        __syncthreads();

        if (kt + 2 < NKT) {
            uint32_t nxt = (uint32_t)(((kt + 2) % 3) * G2_BUF);
            int ko = (kt + 2) * KT;
            #pragma unroll
            for (int it = 0; it < 4; it++) { cp16(dA[it] + nxt, arow[it] + ko); cp16(dB[it] + nxt, brow[it] + ko); }
            cp_commit();
        }

        uint32_t aB = sbase + cur + aOff;
        uint32_t bB = sbase + cur + bOff;
        #pragma unroll
        for (int ks = 0; ks < 4; ks++) {
            uint32_t a[4][4], b[2][4];
            #pragma unroll
            for (int mt = 0; mt < 4; mt++)
                ldsm4(a[mt], aB + mt * 16 * SHB + ks * 32);
            ldsm4(b[0], bB + ks * 32);
            ldsm4(b[1], bB + 16 * SHB + ks * 32);
            #pragma unroll
            for (int mt = 0; mt < 4; mt++)
                #pragma unroll
                for (int nt = 0; nt < 4; nt++) {
                    int g = nt >> 1, h = (nt & 1) * 2;
                    mma16(acc[mt][nt], a[mt], b[g][h], b[g][h + 1]);
                }
        }
    }

    #pragma unroll
    for (int mt = 0; mt < 4; mt++) {
        #pragma unroll
        for (int half = 0; half < 2; half++) {
            int gm = m0 + wm * 64 + mt * 16 + (lane >> 2) + half * 8;
            if (gm < cnt) {
                float w   = g_wt[e * T_TOK + gm];
                int   tok = g_tok[e * T_TOK + gm];
                float* op = out + (size_t)tok * DIM + n0 + wn * 32 + (lane & 3) * 2;
                #pragma unroll
                for (int nt = 0; nt < 4; nt++) {
                    atomicAdd(op + nt * 8 + 0, acc[mt][nt][half * 2 + 0] * w);
                    atomicAdd(op + nt * 8 + 1, acc[mt][nt][half * 2 + 1] * w);
                }
            }
        }
    }
}

// ---------------- launch ----------------
extern "C" void kernel_launch(void* const* d_in, const int* in_sizes, int n_in,
                              void* d_out, int out_size) {
    const float* x         = (const float*)d_in[0];
    const float* gate_w    = (const float*)d_in[1];
    const float* gate_proj = (const float*)d_in[2];
    const float* up_proj   = (const float*)d_in[3];
    const float* down_proj = (const float*)d_in[4];
    float* out = (float*)d_out;

    cudaFuncSetAttribute(k_gemm1, cudaFuncAttributeMaxDynamicSharedMemorySize, G1_SMEM);
    cudaFuncSetAttribute(k_gemm2, cudaFuncAttributeMaxDynamicSharedMemorySize, G2_SMEM);

    cudaMemsetAsync(out, 0, (size_t)out_size * sizeof(float), 0);
    void* cnt_addr = nullptr;
    cudaGetSymbolAddress(&cnt_addr, g_count);
    cudaMemsetAsync(cnt_addr, 0, NE * sizeof(int), 0);

    // prep: router blocks (2 tokens/warp) + wg/wu conversion
    k_prep<<<ROUTB + 2 * CONVB, 256>>>(x, gate_w, gate_proj, up_proj);
    k_gemm1<<<dim3(HIDDEN / 64, T_TOK / 128, NE + 1), 256, G1_SMEM>>>(down_proj);
    k_gemm2<<<dim3(DIM / 128, T_TOK / 128, NE), 256, G2_SMEM>>>(out);
}

// round 15
// speedup vs baseline: 1.0276x; 1.0276x over previous
#include <cuda_runtime.h>
#include <cuda_fp16.h>
#include <math.h>
#include <stdint.h>

#define DIM     1024
#define HIDDEN  1024
#define NE      8
#define T_TOK   32768
#define KT      64          // k-tile in halfs (128B of fp16)
#define NKT     16          // 1024 / 64
#define SHB     144         // padded smem row bytes (72 halfs)

// ---------------- device scratch ----------------
__device__ int    g_count[NE];
__device__ int    g_tok[NE * T_TOK];
__device__ float  g_wt[NE * T_TOK];
__device__ __align__(16) __half g_x16[(size_t)T_TOK * DIM];
__device__ __align__(16) __half g_wg16[(size_t)NE * HIDDEN * DIM];
__device__ __align__(16) __half g_wu16[(size_t)NE * HIDDEN * DIM];
__device__ __align__(16) __half g_wd16[(size_t)NE * DIM * HIDDEN];
__device__ __align__(16) __half g_h[(size_t)NE * T_TOK * HIDDEN];   // uncompacted: [e][slot][H]

// ---------------- helpers ----------------
__device__ __forceinline__ uint32_t sptr(const void* p) {
    return (uint32_t)__cvta_generic_to_shared(p);
}
__device__ __forceinline__ void cp16(uint32_t dst, const void* src) {
    asm volatile("cp.async.cg.shared.global [%0], [%1], 16;" :: "r"(dst), "l"(src));
}
__device__ __forceinline__ void cp_commit() {
    asm volatile("cp.async.commit_group;" ::: "memory");
}
template<int N> __device__ __forceinline__ void cp_wait() {
    asm volatile("cp.async.wait_group %0;" :: "n"(N) : "memory");
}
__device__ __forceinline__ void ldsm4(uint32_t* r, uint32_t a) {
    asm volatile("ldmatrix.sync.aligned.m8n8.x4.shared.b16 {%0,%1,%2,%3}, [%4];"
                 : "=r"(r[0]), "=r"(r[1]), "=r"(r[2]), "=r"(r[3]) : "r"(a));
}
__device__ __forceinline__ void mma16(float* c, const uint32_t* a, uint32_t b0, uint32_t b1) {
    asm volatile("mma.sync.aligned.m16n8k16.row.col.f32.f16.f16.f32 "
                 "{%0,%1,%2,%3},{%4,%5,%6,%7},{%8,%9},{%0,%1,%2,%3};"
                 : "+f"(c[0]), "+f"(c[1]), "+f"(c[2]), "+f"(c[3])
                 : "r"(a[0]), "r"(a[1]), "r"(a[2]), "r"(a[3]), "r"(b0), "r"(b1));
}
__device__ __forceinline__ void red2(float* addr, float a, float b) {
    asm volatile("red.global.add.v2.f32 [%0], {%1, %2};"
                 :: "l"(addr), "f"(a), "f"(b) : "memory");
}
__device__ __forceinline__ float silu(float g) {
    return g * (1.f / (1.f + __expf(-g)));
}

// ---------------- fused prep: wg/wu conversion + router (1 token/warp, x prefetch) ----------------
#define CONVB   (NE * HIDDEN * DIM / 4 / 256)   // 8192 blocks per weight tensor
#define ROUTB   (T_TOK / 8)                     // 4096 router blocks
__global__ __launch_bounds__(256) void k_prep(const float* __restrict__ x,
                                              const float* __restrict__ gate_w,
                                              const float* __restrict__ wg,
                                              const float* __restrict__ wu) {
    int b = blockIdx.x;
    if (b >= ROUTB) {
        int cb    = b - ROUTB;
        int which = cb / CONVB;
        const float* s = (which == 0) ? wg : wu;
        __half* d = (which == 0) ? g_wg16 : g_wu16;
        int i = (cb - which * CONVB) * 256 + threadIdx.x;
        float4 v = ((const float4*)s)[i];
        __half2* o = (__half2*)d + (size_t)i * 2;
        o[0] = __floats2half2_rn(v.x, v.y);
        o[1] = __floats2half2_rn(v.z, v.w);
        return;
    }
    int warp = b * 8 + (threadIdx.x >> 5);
    int lane = threadIdx.x & 31;
    const float* xr = x + (size_t)warp * DIM;
    __half* xo = g_x16 + (size_t)warp * DIM;
    float acc[NE];
    #pragma unroll
    for (int e = 0; e < NE; e++) acc[e] = 0.f;

    float4 xv = *(const float4*)(xr + lane * 4);
    #pragma unroll
    for (int j = 0; j < DIM / 128; j++) {
        int d = j * 128 + lane * 4;
        float4 xn;
        if (j + 1 < DIM / 128) xn = *(const float4*)(xr + d + 128);
        *(__half2*)(xo + d)     = __floats2half2_rn(xv.x, xv.y);
        *(__half2*)(xo + d + 2) = __floats2half2_rn(xv.z, xv.w);
        #pragma unroll
        for (int e = 0; e < NE; e++) {
            float4 gv = *(const float4*)(gate_w + e * DIM + d);
            acc[e] += xv.x * gv.x + xv.y * gv.y + xv.z * gv.z + xv.w * gv.w;
        }
        xv = xn;
    }
    #pragma unroll
    for (int off = 16; off > 0; off >>= 1)
        #pragma unroll
        for (int e = 0; e < NE; e++)
            acc[e] += __shfl_xor_sync(0xffffffffu, acc[e], off);
    if (lane == 0) {
        int i0 = 0;
        #pragma unroll
        for (int e = 1; e < NE; e++) if (acc[e] > acc[i0]) i0 = e;
        int i1 = -1;
        #pragma unroll
        for (int e = 0; e < NE; e++) {
            if (e == i0) continue;
            if (i1 < 0 || acc[e] > acc[i1]) i1 = e;
        }
        float s0 = 1.f / (1.f + __expf(-acc[i0]));
        float s1 = 1.f / (1.f + __expf(-acc[i1]));
        float inv = 1.f / (s0 + s1 + 1e-9f);
        int p0 = atomicAdd(&g_count[i0], 1);
        g_tok[i0 * T_TOK + p0] = warp; g_wt[i0 * T_TOK + p0] = s0 * inv;
        int p1 = atomicAdd(&g_count[i1], 1);
        g_tok[i1 * T_TOK + p1] = warp; g_wt[i1 * T_TOK + p1] = s1 * inv;
    }
}

// ---------------- GEMM1 (fp16 mma): h = silu(Xg Wg^T) * (Xg Wu^T) ----------------
// Block 128(M) x 64(N) dual-B, 256 thr, 3-stage cp.async pipeline, one barrier/iter.
// z-slice NE carries the down_proj fp32->fp16 conversion (rides gemm1's idle DRAM bandwidth).
#define G1_BUF  (256 * SHB)
#define G1_SMEM (3 * G1_BUF)
__global__ __launch_bounds__(256, 2) void k_gemm1(const float* __restrict__ wd) {
    extern __shared__ char smem[];
    if (blockIdx.z == NE) {
        int bi = blockIdx.y * gridDim.x + blockIdx.x;          // 0..4095
        int i0 = (bi * 256 + (int)threadIdx.x) * 2;
        #pragma unroll
        for (int k = 0; k < 2; k++) {
            int i = i0 + k;
            float4 v = ((const float4*)wd)[i];
            __half2* o = (__half2*)g_wd16 + (size_t)i * 2;
            o[0] = __floats2half2_rn(v.x, v.y);
            o[1] = __floats2half2_rn(v.z, v.w);
        }
        return;
    }
    int e   = blockIdx.z;
    int cnt = g_count[e];
    int m0  = blockIdx.y * 128;
    if (m0 >= cnt) return;
    int n0  = blockIdx.x * 64;
    int tid = threadIdx.x, lane = tid & 31, wid = tid >> 5;
    int wm  = wid & 3, wn = wid >> 2;

    const __half* Wg = g_wg16 + (size_t)e * HIDDEN * DIM;
    const __half* Wu = g_wu16 + (size_t)e * HIDDEN * DIM;

    const __half* arow[4];
    #pragma unroll
    for (int it = 0; it < 4; it++) {
        int flat = tid + it * 256;
        int m    = flat >> 3;
        int gm   = m0 + m;
        int tok  = g_tok[e * T_TOK + (gm < cnt ? gm : 0)];
        arow[it] = g_x16 + (size_t)tok * DIM + (flat & 7) * 8;
    }
    const __half* grow[2];
    const __half* urow[2];
    #pragma unroll
    for (int it = 0; it < 2; it++) {
        int flat = tid + it * 256;
        int n    = flat >> 3;
        grow[it] = Wg + (size_t)(n0 + n) * DIM + (flat & 7) * 8;
        urow[it] = Wu + (size_t)(n0 + n) * DIM + (flat & 7) * 8;
    }
    uint32_t sbase = sptr(smem);
    uint32_t dA[4], dG[2], dU[2];
    #pragma unroll
    for (int it = 0; it < 4; it++) {
        int flat = tid + it * 256;
        dA[it] = sbase + (uint32_t)((flat >> 3) * SHB + (flat & 7) * 16);
    }
    #pragma unroll
    for (int it = 0; it < 2; it++) {
        int flat = tid + it * 256;
        dG[it] = sbase + (uint32_t)(128 * SHB + (flat >> 3) * SHB + (flat & 7) * 16);
        dU[it] = sbase + (uint32_t)(192 * SHB + (flat >> 3) * SHB + (flat & 7) * 16);
    }

    float accg[2][4][4], accu[2][4][4];
    #pragma unroll
    for (int mt = 0; mt < 2; mt++)
        #pragma unroll
        for (int nt = 0; nt < 4; nt++)
            #pragma unroll
            for (int i = 0; i < 4; i++) { accg[mt][nt][i] = 0.f; accu[mt][nt][i] = 0.f; }

    uint32_t aOff = (uint32_t)((wm * 32 + (lane & 15)) * SHB + ((lane >> 4) & 1) * 16);
    uint32_t bRow = (uint32_t)(wn * 32 + (lane & 7) + ((lane >> 4) & 1) * 8);
    uint32_t gOff = 128 * SHB + bRow * SHB + ((lane >> 3) & 1) * 16;
    uint32_t uOff = 192 * SHB + bRow * SHB + ((lane >> 3) & 1) * 16;

    #pragma unroll
    for (int it = 0; it < 4; it++) cp16(dA[it], arow[it]);
    #pragma unroll
    for (int it = 0; it < 2; it++) { cp16(dG[it], grow[it]); cp16(dU[it], urow[it]); }
    cp_commit();
    #pragma unroll
    for (int it = 0; it < 4; it++) cp16(dA[it] + G1_BUF, arow[it] + KT);
    #pragma unroll
    for (int it = 0; it < 2; it++) { cp16(dG[it] + G1_BUF, grow[it] + KT); cp16(dU[it] + G1_BUF, urow[it] + KT); }
    cp_commit();

    for (int kt = 0; kt < NKT; kt++) {
        uint32_t cur = (uint32_t)((kt % 3) * G1_BUF);
        if (kt == NKT - 1) cp_wait<0>(); else cp_wait<1>();
        __syncthreads();

        if (kt + 2 < NKT) {
            uint32_t nxt = (uint32_t)(((kt + 2) % 3) * G1_BUF);
            int ko = (kt + 2) * KT;
            #pragma unroll
            for (int it = 0; it < 4; it++) cp16(dA[it] + nxt, arow[it] + ko);
            #pragma unroll
            for (int it = 0; it < 2; it++) { cp16(dG[it] + nxt, grow[it] + ko); cp16(dU[it] + nxt, urow[it] + ko); }
            cp_commit();
        }

        uint32_t aB = sbase + cur + aOff;
        uint32_t gB = sbase + cur + gOff;
        uint32_t uB = sbase + cur + uOff;
        #pragma unroll
        for (int ks = 0; ks < 4; ks++) {
            uint32_t a[2][4], bg[2][4], bu[2][4];
            ldsm4(a[0], aB + ks * 32);
            ldsm4(a[1], aB + 16 * SHB + ks * 32);
            ldsm4(bg[0], gB + ks * 32);
            ldsm4(bg[1], gB + 16 * SHB + ks * 32);
            ldsm4(bu[0], uB + ks * 32);
            ldsm4(bu[1], uB + 16 * SHB + ks * 32);
            #pragma unroll
            for (int mt = 0; mt < 2; mt++)
                #pragma unroll
                for (int nt = 0; nt < 4; nt++) {
                    int g = nt >> 1, h = (nt & 1) * 2;
                    mma16(accg[mt][nt], a[mt], bg[g][h], bg[g][h + 1]);
                    mma16(accu[mt][nt], a[mt], bu[g][h], bu[g][h + 1]);
                }
        }
    }

    size_t base = (size_t)e * T_TOK;
    #pragma unroll
    for (int mt = 0; mt < 2; mt++) {
        #pragma unroll
        for (int half = 0; half < 2; half++) {
            int gm = m0 + wm * 32 + mt * 16 + (lane >> 2) + half * 8;
            if (gm < cnt) {
                __half* hp = &g_h[(base + gm) * HIDDEN + n0 + wn * 32 + (lane & 3) * 2];
                #pragma unroll
                for (int nt = 0; nt < 4; nt++) {
                    float gx = accg[mt][nt][half * 2 + 0], ux = accu[mt][nt][half * 2 + 0];
                    float gy = accg[mt][nt][half * 2 + 1], uy = accu[mt][nt][half * 2 + 1];
                    *(__half2*)(hp + nt * 8) = __floats2half2_rn(silu(gx) * ux, silu(gy) * uy);
                }
            }
        }
    }
}

// ---------------- GEMM2 (fp16 mma): out += (h Wd^T) * wt  (red.v2, 2 adds/elem) ----------------
#define G2_BUF  (256 * SHB)
#define G2_SMEM (3 * G2_BUF)
__global__ __launch_bounds__(256, 2) void k_gemm2(float* __restrict__ out) {
    extern __shared__ char smem[];
    int e   = blockIdx.z;
    int cnt = g_count[e];
    int m0  = blockIdx.y * 128;
    if (m0 >= cnt) return;
    int n0  = blockIdx.x * 128;
    int tid = threadIdx.x, lane = tid & 31, wid = tid >> 5;
    int wm  = wid & 1, wn = wid >> 1;

    const __half* Wd = g_wd16 + (size_t)e * DIM * HIDDEN;
    size_t base = (size_t)e * T_TOK;

    const __half* arow[4];
    const __half* brow[4];
    #pragma unroll
    for (int it = 0; it < 4; it++) {
        int flat = tid + it * 256;
        int m    = flat >> 3;
        int gm   = m0 + m;
        arow[it] = g_h + (base + (gm < cnt ? gm : 0)) * HIDDEN + (flat & 7) * 8;
        brow[it] = Wd + (size_t)(n0 + m) * HIDDEN + (flat & 7) * 8;
    }
    uint32_t sbase = sptr(smem);
    uint32_t dA[4], dB[4];
    #pragma unroll
    for (int it = 0; it < 4; it++) {
        int flat = tid + it * 256;
        dA[it] = sbase + (uint32_t)((flat >> 3) * SHB + (flat & 7) * 16);
        dB[it] = dA[it] + 128 * SHB;
    }

    float acc[4][4][4];
    #pragma unroll
    for (int mt = 0; mt < 4; mt++)
        #pragma unroll
        for (int nt = 0; nt < 4; nt++)
            #pragma unroll
            for (int i = 0; i < 4; i++) acc[mt][nt][i] = 0.f;

    uint32_t aOff = (uint32_t)((wm * 64 + (lane & 15)) * SHB + ((lane >> 4) & 1) * 16);
    uint32_t bOff = 128 * SHB +
                    (uint32_t)((wn * 32 + (lane & 7) + ((lane >> 4) & 1) * 8) * SHB +
                               ((lane >> 3) & 1) * 16);

    #pragma unroll
    for (int it = 0; it < 4; it++) { cp16(dA[it], arow[it]); cp16(dB[it], brow[it]); }
    cp_commit();
    #pragma unroll
    for (int it = 0; it < 4; it++) { cp16(dA[it] + G2_BUF, arow[it] + KT); cp16(dB[it] + G2_BUF, brow[it] + KT); }
    cp_commit();

    for (int kt = 0; kt < NKT; kt++) {
        uint32_t cur = (uint32_t)((kt % 3) * G2_BUF);
        if (kt == NKT - 1) cp_wait<0>(); else cp_wait<1>();
        __syncthreads();

        if (kt + 2 < NKT) {
            uint32_t nxt = (uint32_t)(((kt + 2) % 3) * G2_BUF);
            int ko = (kt + 2) * KT;
            #pragma unroll
            for (int it = 0; it < 4; it++) { cp16(dA[it] + nxt, arow[it] + ko); cp16(dB[it] + nxt, brow[it] + ko); }
            cp_commit();
        }

        uint32_t aB = sbase + cur + aOff;
        uint32_t bB = sbase + cur + bOff;
        #pragma unroll
        for (int ks = 0; ks < 4; ks++) {
            uint32_t a[4][4], b[2][4];
            #pragma unroll
            for (int mt = 0; mt < 4; mt++)
                ldsm4(a[mt], aB + mt * 16 * SHB + ks * 32);
            ldsm4(b[0], bB + ks * 32);
            ldsm4(b[1], bB + 16 * SHB + ks * 32);
            #pragma unroll
            for (int mt = 0; mt < 4; mt++)
                #pragma unroll
                for (int nt = 0; nt < 4; nt++) {
                    int g = nt >> 1, h = (nt & 1) * 2;
                    mma16(acc[mt][nt], a[mt], b[g][h], b[g][h + 1]);
                }
        }
    }

    #pragma unroll
    for (int mt = 0; mt < 4; mt++) {
        #pragma unroll
        for (int half = 0; half < 2; half++) {
            int gm = m0 + wm * 64 + mt * 16 + (lane >> 2) + half * 8;
            if (gm < cnt) {
                float w   = g_wt[e * T_TOK + gm];
                int   tok = g_tok[e * T_TOK + gm];
                float* op = out + (size_t)tok * DIM + n0 + wn * 32 + (lane & 3) * 2;
                #pragma unroll
                for (int nt = 0; nt < 4; nt++)
                    red2(op + nt * 8,
                         acc[mt][nt][half * 2 + 0] * w,
                         acc[mt][nt][half * 2 + 1] * w);
            }
        }
    }
}

// ---------------- launch ----------------
extern "C" void kernel_launch(void* const* d_in, const int* in_sizes, int n_in,
                              void* d_out, int out_size) {
    const float* x         = (const float*)d_in[0];
    const float* gate_w    = (const float*)d_in[1];
    const float* gate_proj = (const float*)d_in[2];
    const float* up_proj   = (const float*)d_in[3];
    const float* down_proj = (const float*)d_in[4];
    float* out = (float*)d_out;

    cudaFuncSetAttribute(k_gemm1, cudaFuncAttributeMaxDynamicSharedMemorySize, G1_SMEM);
    cudaFuncSetAttribute(k_gemm2, cudaFuncAttributeMaxDynamicSharedMemorySize, G2_SMEM);

    cudaMemsetAsync(out, 0, (size_t)out_size * sizeof(float), 0);
    void* cnt_addr = nullptr;
    cudaGetSymbolAddress(&cnt_addr, g_count);
    cudaMemsetAsync(cnt_addr, 0, NE * sizeof(int), 0);

    k_prep<<<ROUTB + 2 * CONVB, 256>>>(x, gate_w, gate_proj, up_proj);
    k_gemm1<<<dim3(HIDDEN / 64, T_TOK / 128, NE + 1), 256, G1_SMEM>>>(down_proj);
    k_gemm2<<<dim3(DIM / 128, T_TOK / 128, NE), 256, G2_SMEM>>>(out);
}

// round 16
// speedup vs baseline: 1.0307x; 1.0030x over previous
#include <cuda_runtime.h>
#include <cuda_fp16.h>
#include <math.h>
#include <stdint.h>

#define DIM     1024
#define HIDDEN  1024
#define NE      8
#define T_TOK   32768
#define KT      64          // k-tile in halfs (128B of fp16)
#define NKT     16          // 1024 / 64
#define SHB     144         // padded smem row bytes (72 halfs)

// ---------------- device scratch ----------------
__device__ int    g_count[NE];
__device__ int    g_tok[NE * T_TOK];
__device__ float  g_wt[NE * T_TOK];
__device__ __align__(16) __half g_x16[(size_t)T_TOK * DIM];
__device__ __align__(16) __half g_wg16[(size_t)NE * HIDDEN * DIM];
__device__ __align__(16) __half g_wu16[(size_t)NE * HIDDEN * DIM];
__device__ __align__(16) __half g_wd16[(size_t)NE * DIM * HIDDEN];
__device__ __align__(16) __half g_h[(size_t)NE * T_TOK * HIDDEN];   // uncompacted: [e][slot][H]

// ---------------- helpers ----------------
__device__ __forceinline__ uint32_t sptr(const void* p) {
    return (uint32_t)__cvta_generic_to_shared(p);
}
__device__ __forceinline__ void cp16(uint32_t dst, const void* src) {
    asm volatile("cp.async.cg.shared.global [%0], [%1], 16;" :: "r"(dst), "l"(src));
}
__device__ __forceinline__ void cp_commit() {
    asm volatile("cp.async.commit_group;" ::: "memory");
}
template<int N> __device__ __forceinline__ void cp_wait() {
    asm volatile("cp.async.wait_group %0;" :: "n"(N) : "memory");
}
__device__ __forceinline__ void ldsm4(uint32_t* r, uint32_t a) {
    asm volatile("ldmatrix.sync.aligned.m8n8.x4.shared.b16 {%0,%1,%2,%3}, [%4];"
                 : "=r"(r[0]), "=r"(r[1]), "=r"(r[2]), "=r"(r[3]) : "r"(a));
}
__device__ __forceinline__ void mma16(float* c, const uint32_t* a, uint32_t b0, uint32_t b1) {
    asm volatile("mma.sync.aligned.m16n8k16.row.col.f32.f16.f16.f32 "
                 "{%0,%1,%2,%3},{%4,%5,%6,%7},{%8,%9},{%0,%1,%2,%3};"
                 : "+f"(c[0]), "+f"(c[1]), "+f"(c[2]), "+f"(c[3])
                 : "r"(a[0]), "r"(a[1]), "r"(a[2]), "r"(a[3]), "r"(b0), "r"(b1));
}
__device__ __forceinline__ void red2(float* addr, float a, float b) {
    asm volatile("red.global.add.v2.f32 [%0], {%1, %2};"
                 :: "l"(addr), "f"(a), "f"(b) : "memory");
}
__device__ __forceinline__ float silu(float g) {
    return g * (1.f / (1.f + __expf(-g)));
}

// ---------------- fused prep: router + wg/wu conversion + out zeroing ----------------
#define CONVB   (NE * HIDDEN * DIM / 4 / 256)   // 8192 blocks per weight tensor
#define ROUTB   (T_TOK / 8)                     // 4096 router blocks
#define ZEROB   8192                            // out-zero blocks: 8192 x 16KB = 128MB
__global__ __launch_bounds__(256) void k_prep(const float* __restrict__ x,
                                              const float* __restrict__ gate_w,
                                              const float* __restrict__ wg,
                                              const float* __restrict__ wu,
                                              float* __restrict__ out) {
    int b = blockIdx.x;
    if (b >= ROUTB + 2 * CONVB) {
        // -------- out zeroing: 4 x float4 per thread --------
        int zb = b - (ROUTB + 2 * CONVB);
        float4* o = (float4*)out + (size_t)zb * 1024 + threadIdx.x;
        float4 z = make_float4(0.f, 0.f, 0.f, 0.f);
        o[0] = z; o[256] = z; o[512] = z; o[768] = z;
        return;
    }
    if (b >= ROUTB) {
        // -------- weight conversion (gate_proj / up_proj) --------
        int cb    = b - ROUTB;
        int which = cb / CONVB;
        const float* s = (which == 0) ? wg : wu;
        __half* d = (which == 0) ? g_wg16 : g_wu16;
        int i = (cb - which * CONVB) * 256 + threadIdx.x;
        float4 v = ((const float4*)s)[i];
        __half2* o = (__half2*)d + (size_t)i * 2;
        o[0] = __floats2half2_rn(v.x, v.y);
        o[1] = __floats2half2_rn(v.z, v.w);
        return;
    }
    // -------- router (one warp per token, fused x fp16 conversion, x prefetch) --------
    int warp = b * 8 + (threadIdx.x >> 5);
    int lane = threadIdx.x & 31;
    const float* xr = x + (size_t)warp * DIM;
    __half* xo = g_x16 + (size_t)warp * DIM;
    float acc[NE];
    #pragma unroll
    for (int e = 0; e < NE; e++) acc[e] = 0.f;

    float4 xv = *(const float4*)(xr + lane * 4);
    #pragma unroll
    for (int j = 0; j < DIM / 128; j++) {
        int d = j * 128 + lane * 4;
        float4 xn;
        if (j + 1 < DIM / 128) xn = *(const float4*)(xr + d + 128);
        *(__half2*)(xo + d)     = __floats2half2_rn(xv.x, xv.y);
        *(__half2*)(xo + d + 2) = __floats2half2_rn(xv.z, xv.w);
        #pragma unroll
        for (int e = 0; e < NE; e++) {
            float4 gv = *(const float4*)(gate_w + e * DIM + d);
            acc[e] += xv.x * gv.x + xv.y * gv.y + xv.z * gv.z + xv.w * gv.w;
        }
        xv = xn;
    }
    #pragma unroll
    for (int off = 16; off > 0; off >>= 1)
        #pragma unroll
        for (int e = 0; e < NE; e++)
            acc[e] += __shfl_xor_sync(0xffffffffu, acc[e], off);
    if (lane == 0) {
        int i0 = 0;
        #pragma unroll
        for (int e = 1; e < NE; e++) if (acc[e] > acc[i0]) i0 = e;
        int i1 = -1;
        #pragma unroll
        for (int e = 0; e < NE; e++) {
            if (e == i0) continue;
            if (i1 < 0 || acc[e] > acc[i1]) i1 = e;
        }
        float s0 = 1.f / (1.f + __expf(-acc[i0]));
        float s1 = 1.f / (1.f + __expf(-acc[i1]));
        float inv = 1.f / (s0 + s1 + 1e-9f);
        int p0 = atomicAdd(&g_count[i0], 1);
        g_tok[i0 * T_TOK + p0] = warp; g_wt[i0 * T_TOK + p0] = s0 * inv;
        int p1 = atomicAdd(&g_count[i1], 1);
        g_tok[i1 * T_TOK + p1] = warp; g_wt[i1 * T_TOK + p1] = s1 * inv;
    }
}

// ---------------- GEMM1 (fp16 mma): h = silu(Xg Wg^T) * (Xg Wu^T) ----------------
// Block 128(M) x 64(N) dual-B, 256 thr, 3-stage cp.async pipeline, one barrier/iter.
// z-slice NE carries the down_proj fp32->fp16 conversion (rides gemm1's idle DRAM bandwidth).
#define G1_BUF  (256 * SHB)
#define G1_SMEM (3 * G1_BUF)
__global__ __launch_bounds__(256, 2) void k_gemm1(const float* __restrict__ wd) {
    extern __shared__ char smem[];
    if (blockIdx.z == NE) {
        int bi = blockIdx.y * gridDim.x + blockIdx.x;          // 0..4095
        int i0 = (bi * 256 + (int)threadIdx.x) * 2;
        #pragma unroll
        for (int k = 0; k < 2; k++) {
            int i = i0 + k;
            float4 v = ((const float4*)wd)[i];
            __half2* o = (__half2*)g_wd16 + (size_t)i * 2;
            o[0] = __floats2half2_rn(v.x, v.y);
            o[1] = __floats2half2_rn(v.z, v.w);
        }
        return;
    }
    int e   = blockIdx.z;
    int cnt = g_count[e];
    int m0  = blockIdx.y * 128;
    if (m0 >= cnt) return;
    int n0  = blockIdx.x * 64;
    int tid = threadIdx.x, lane = tid & 31, wid = tid >> 5;
    int wm  = wid & 3, wn = wid >> 2;

    const __half* Wg = g_wg16 + (size_t)e * HIDDEN * DIM;
    const __half* Wu = g_wu16 + (size_t)e * HIDDEN * DIM;

    const __half* arow[4];
    #pragma unroll
    for (int it = 0; it < 4; it++) {
        int flat = tid + it * 256;
        int m    = flat >> 3;
        int gm   = m0 + m;
        int tok  = g_tok[e * T_TOK + (gm < cnt ? gm : 0)];
        arow[it] = g_x16 + (size_t)tok * DIM + (flat & 7) * 8;
    }
    const __half* grow[2];
    const __half* urow[2];
    #pragma unroll
    for (int it = 0; it < 2; it++) {
        int flat = tid + it * 256;
        int n    = flat >> 3;
        grow[it] = Wg + (size_t)(n0 + n) * DIM + (flat & 7) * 8;
        urow[it] = Wu + (size_t)(n0 + n) * DIM + (flat & 7) * 8;
    }
    uint32_t sbase = sptr(smem);
    uint32_t dA[4], dG[2], dU[2];
    #pragma unroll
    for (int it = 0; it < 4; it++) {
        int flat = tid + it * 256;
        dA[it] = sbase + (uint32_t)((flat >> 3) * SHB + (flat & 7) * 16);
    }
    #pragma unroll
    for (int it = 0; it < 2; it++) {
        int flat = tid + it * 256;
        dG[it] = sbase + (uint32_t)(128 * SHB + (flat >> 3) * SHB + (flat & 7) * 16);
        dU[it] = sbase + (uint32_t)(192 * SHB + (flat >> 3) * SHB + (flat & 7) * 16);
    }

    float accg[2][4][4], accu[2][4][4];
    #pragma unroll
    for (int mt = 0; mt < 2; mt++)
        #pragma unroll
        for (int nt = 0; nt < 4; nt++)
            #pragma unroll
            for (int i = 0; i < 4; i++) { accg[mt][nt][i] = 0.f; accu[mt][nt][i] = 0.f; }

    uint32_t aOff = (uint32_t)((wm * 32 + (lane & 15)) * SHB + ((lane >> 4) & 1) * 16);
    uint32_t bRow = (uint32_t)(wn * 32 + (lane & 7) + ((lane >> 4) & 1) * 8);
    uint32_t gOff = 128 * SHB + bRow * SHB + ((lane >> 3) & 1) * 16;
    uint32_t uOff = 192 * SHB + bRow * SHB + ((lane >> 3) & 1) * 16;

    #pragma unroll
    for (int it = 0; it < 4; it++) cp16(dA[it], arow[it]);
    #pragma unroll
    for (int it = 0; it < 2; it++) { cp16(dG[it], grow[it]); cp16(dU[it], urow[it]); }
    cp_commit();
    #pragma unroll
    for (int it = 0; it < 4; it++) cp16(dA[it] + G1_BUF, arow[it] + KT);
    #pragma unroll
    for (int it = 0; it < 2; it++) { cp16(dG[it] + G1_BUF, grow[it] + KT); cp16(dU[it] + G1_BUF, urow[it] + KT); }
    cp_commit();

    for (int kt = 0; kt < NKT; kt++) {
        uint32_t cur = (uint32_t)((kt % 3) * G1_BUF);
        if (kt == NKT - 1) cp_wait<0>(); else cp_wait<1>();
        __syncthreads();

        if (kt + 2 < NKT) {
            uint32_t nxt = (uint32_t)(((kt + 2) % 3) * G1_BUF);
            int ko = (kt + 2) * KT;
            #pragma unroll
            for (int it = 0; it < 4; it++) cp16(dA[it] + nxt, arow[it] + ko);
            #pragma unroll
            for (int it = 0; it < 2; it++) { cp16(dG[it] + nxt, grow[it] + ko); cp16(dU[it] + nxt, urow[it] + ko); }
            cp_commit();
        }

        uint32_t aB = sbase + cur + aOff;
        uint32_t gB = sbase + cur + gOff;
        uint32_t uB = sbase + cur + uOff;
        #pragma unroll
        for (int ks = 0; ks < 4; ks++) {
            uint32_t a[2][4], bg[2][4], bu[2][4];
            ldsm4(a[0], aB + ks * 32);
            ldsm4(a[1], aB + 16 * SHB + ks * 32);
            ldsm4(bg[0], gB + ks * 32);
            ldsm4(bg[1], gB + 16 * SHB + ks * 32);
            ldsm4(bu[0], uB + ks * 32);
            ldsm4(bu[1], uB + 16 * SHB + ks * 32);
            #pragma unroll
            for (int mt = 0; mt < 2; mt++)
                #pragma unroll
                for (int nt = 0; nt < 4; nt++) {
                    int g = nt >> 1, h = (nt & 1) * 2;
                    mma16(accg[mt][nt], a[mt], bg[g][h], bg[g][h + 1]);
                    mma16(accu[mt][nt], a[mt], bu[g][h], bu[g][h + 1]);
                }
        }
    }

    size_t base = (size_t)e * T_TOK;
    #pragma unroll
    for (int mt = 0; mt < 2; mt++) {
        #pragma unroll
        for (int half = 0; half < 2; half++) {
            int gm = m0 + wm * 32 + mt * 16 + (lane >> 2) + half * 8;
            if (gm < cnt) {
                __half* hp = &g_h[(base + gm) * HIDDEN + n0 + wn * 32 + (lane & 3) * 2];
                #pragma unroll
                for (int nt = 0; nt < 4; nt++) {
                    float gx = accg[mt][nt][half * 2 + 0], ux = accu[mt][nt][half * 2 + 0];
                    float gy = accg[mt][nt][half * 2 + 1], uy = accu[mt][nt][half * 2 + 1];
                    *(__half2*)(hp + nt * 8) = __floats2half2_rn(silu(gx) * ux, silu(gy) * uy);
                }
            }
        }
    }
}

// ---------------- GEMM2 (fp16 mma): out += (h Wd^T) * wt  (red.v2, 2 adds/elem) ----------------
#define G2_BUF  (256 * SHB)
#define G2_SMEM (3 * G2_BUF)
__global__ __launch_bounds__(256, 2) void k_gemm2(float* __restrict__ out) {
    extern __shared__ char smem[];
    int e   = blockIdx.z;
    int cnt = g_count[e];
    int m0  = blockIdx.y * 128;
    if (m0 >= cnt) return;
    int n0  = blockIdx.x * 128;
    int tid = threadIdx.x, lane = tid & 31, wid = tid >> 5;
    int wm  = wid & 1, wn = wid >> 1;

    const __half* Wd = g_wd16 + (size_t)e * DIM * HIDDEN;
    size_t base = (size_t)e * T_TOK;

    const __half* arow[4];
    const __half* brow[4];
    #pragma unroll
    for (int it = 0; it < 4; it++) {
        int flat = tid + it * 256;
        int m    = flat >> 3;
        int gm   = m0 + m;
        arow[it] = g_h + (base + (gm < cnt ? gm : 0)) * HIDDEN + (flat & 7) * 8;
        brow[it] = Wd + (size_t)(n0 + m) * HIDDEN + (flat & 7) * 8;
    }
    uint32_t sbase = sptr(smem);
    uint32_t dA[4], dB[4];
    #pragma unroll
    for (int it = 0; it < 4; it++) {
        int flat = tid + it * 256;
        dA[it] = sbase + (uint32_t)((flat >> 3) * SHB + (flat & 7) * 16);
        dB[it] = dA[it] + 128 * SHB;
    }

    float acc[4][4][4];
    #pragma unroll
    for (int mt = 0; mt < 4; mt++)
        #pragma unroll
        for (int nt = 0; nt < 4; nt++)
            #pragma unroll
            for (int i = 0; i < 4; i++) acc[mt][nt][i] = 0.f;

    uint32_t aOff = (uint32_t)((wm * 64 + (lane & 15)) * SHB + ((lane >> 4) & 1) * 16);
    uint32_t bOff = 128 * SHB +
                    (uint32_t)((wn * 32 + (lane & 7) + ((lane >> 4) & 1) * 8) * SHB +
                               ((lane >> 3) & 1) * 16);

    #pragma unroll
    for (int it = 0; it < 4; it++) { cp16(dA[it], arow[it]); cp16(dB[it], brow[it]); }
    cp_commit();
    #pragma unroll
    for (int it = 0; it < 4; it++) { cp16(dA[it] + G2_BUF, arow[it] + KT); cp16(dB[it] + G2_BUF, brow[it] + KT); }
    cp_commit();

    for (int kt = 0; kt < NKT; kt++) {
        uint32_t cur = (uint32_t)((kt % 3) * G2_BUF);
        if (kt == NKT - 1) cp_wait<0>(); else cp_wait<1>();
        __syncthreads();

        if (kt + 2 < NKT) {
            uint32_t nxt = (uint32_t)(((kt + 2) % 3) * G2_BUF);
            int ko = (kt + 2) * KT;
            #pragma unroll
            for (int it = 0; it < 4; it++) { cp16(dA[it] + nxt, arow[it] + ko); cp16(dB[it] + nxt, brow[it] + ko); }
            cp_commit();
        }

        uint32_t aB = sbase + cur + aOff;
        uint32_t bB = sbase + cur + bOff;
        #pragma unroll
        for (int ks = 0; ks < 4; ks++) {
            uint32_t a[4][4], b[2][4];
            #pragma unroll
            for (int mt = 0; mt < 4; mt++)
                ldsm4(a[mt], aB + mt * 16 * SHB + ks * 32);
            ldsm4(b[0], bB + ks * 32);
            ldsm4(b[1], bB + 16 * SHB + ks * 32);
            #pragma unroll
            for (int mt = 0; mt < 4; mt++)
                #pragma unroll
                for (int nt = 0; nt < 4; nt++) {
                    int g = nt >> 1, h = (nt & 1) * 2;
                    mma16(acc[mt][nt], a[mt], b[g][h], b[g][h + 1]);
                }
        }
    }

    #pragma unroll
    for (int mt = 0; mt < 4; mt++) {
        #pragma unroll
        for (int half = 0; half < 2; half++) {
            int gm = m0 + wm * 64 + mt * 16 + (lane >> 2) + half * 8;
            if (gm < cnt) {
                float w   = g_wt[e * T_TOK + gm];
                int   tok = g_tok[e * T_TOK + gm];
                float* op = out + (size_t)tok * DIM + n0 + wn * 32 + (lane & 3) * 2;
                #pragma unroll
                for (int nt = 0; nt < 4; nt++)
                    red2(op + nt * 8,
                         acc[mt][nt][half * 2 + 0] * w,
                         acc[mt][nt][half * 2 + 1] * w);
            }
        }
    }
}

// ---------------- launch ----------------
extern "C" void kernel_launch(void* const* d_in, const int* in_sizes, int n_in,
                              void* d_out, int out_size) {
    const float* x         = (const float*)d_in[0];
    const float* gate_w    = (const float*)d_in[1];
    const float* gate_proj = (const float*)d_in[2];
    const float* up_proj   = (const float*)d_in[3];
    const float* down_proj = (const float*)d_in[4];
    float* out = (float*)d_out;

    cudaFuncSetAttribute(k_gemm1, cudaFuncAttributeMaxDynamicSharedMemorySize, G1_SMEM);
    cudaFuncSetAttribute(k_gemm2, cudaFuncAttributeMaxDynamicSharedMemorySize, G2_SMEM);

    void* cnt_addr = nullptr;
    cudaGetSymbolAddress(&cnt_addr, g_count);
    cudaMemsetAsync(cnt_addr, 0, NE * sizeof(int), 0);

    // prep: router + wg/wu conversion + out zeroing (rides prep's idle bandwidth)
    k_prep<<<ROUTB + 2 * CONVB + ZEROB, 256>>>(x, gate_w, gate_proj, up_proj, out);
    k_gemm1<<<dim3(HIDDEN / 64, T_TOK / 128, NE + 1), 256, G1_SMEM>>>(down_proj);
    k_gemm2<<<dim3(DIM / 128, T_TOK / 128, NE), 256, G2_SMEM>>>(out);
}